// round 4
// baseline (speedup 1.0000x reference)
#include <cuda_runtime.h>
#include <cstdint>

// CausalConv1d (R4): out[b,h] = sum_k state/x taps * w[h,k] + bias[h]
// new_state[b,h,:] = {state[b,h,1], state[b,h,2], x[b,h]}
//
// One-shot flat mapping (R2 structure, which benched 96.3us) with 8 pairs per
// thread: 8 front-batched LDG.128 (128B in flight per thread) to raise MLP and
// push DRAM busy above R2's 67.6%.

#define HIDDEN 4096
#define BATCH  4096
#define PAIRS  ((int64_t)BATCH * HIDDEN)          // 16,777,216
#define PAIRS_PER_THREAD 8
#define NTHREADS_TOTAL (PAIRS / PAIRS_PER_THREAD) // 2,097,152

__global__ void __launch_bounds__(256, 8)
causal_conv1d_kernel(const float* __restrict__ x,
                     const float* __restrict__ state,
                     const float* __restrict__ weight,   // [HIDDEN,4]
                     const float* __restrict__ bias,     // [HIDDEN]
                     float* __restrict__ out,            // [BATCH,HIDDEN]
                     float* __restrict__ new_state)      // [BATCH,HIDDEN,3]
{
    int64_t t = (int64_t)blockIdx.x * blockDim.x + threadIdx.x;

    int64_t p0 = t * PAIRS_PER_THREAD;        // 8 consecutive (b,h) pairs, same row
    int     h0 = (int)(p0 & (HIDDEN - 1));    // 8 consecutive h's (HIDDEN % 8 == 0)

    // ---- front-batched streaming loads (all LDG.128, fully coalesced) ----
    const float4* xp = reinterpret_cast<const float4*>(x + p0);
    const float4 xa = xp[0];                  // X0..X3
    const float4 xb = xp[1];                  // X4..X7

    const float4* sp = reinterpret_cast<const float4*>(state + p0 * 3);
    const float4 s0 = sp[0];   // S0..S3
    const float4 s1 = sp[1];   // S4..S7
    const float4 s2 = sp[2];   // S8..S11
    const float4 s3 = sp[3];   // S12..S15
    const float4 s4 = sp[4];   // S16..S19
    const float4 s5 = sp[5];   // S20..S23

    // ---- weights/bias (L2-resident, 64KB+16KB working set) ----
    const float4* wp = reinterpret_cast<const float4*>(weight + (int64_t)h0 * 4);
    const float4 w0 = wp[0], w1 = wp[1], w2 = wp[2], w3 = wp[3];
    const float4 w4 = wp[4], w5 = wp[5], w6 = wp[6], w7 = wp[7];
    const float4* bp = reinterpret_cast<const float4*>(bias + h0);
    const float4 ba = bp[0], bb = bp[1];

    // ---- compute: pair j uses S[3j],S[3j+1],S[3j+2], X[j] ----
    float4 oa, ob;
    oa.x = fmaf(s0.x, w0.x, fmaf(s0.y, w0.y, fmaf(s0.z, w0.z, fmaf(xa.x, w0.w, ba.x))));
    oa.y = fmaf(s0.w, w1.x, fmaf(s1.x, w1.y, fmaf(s1.y, w1.z, fmaf(xa.y, w1.w, ba.y))));
    oa.z = fmaf(s1.z, w2.x, fmaf(s1.w, w2.y, fmaf(s2.x, w2.z, fmaf(xa.z, w2.w, ba.z))));
    oa.w = fmaf(s2.y, w3.x, fmaf(s2.z, w3.y, fmaf(s2.w, w3.z, fmaf(xa.w, w3.w, ba.w))));
    ob.x = fmaf(s3.x, w4.x, fmaf(s3.y, w4.y, fmaf(s3.z, w4.z, fmaf(xb.x, w4.w, bb.x))));
    ob.y = fmaf(s3.w, w5.x, fmaf(s4.x, w5.y, fmaf(s4.y, w5.z, fmaf(xb.y, w5.w, bb.y))));
    ob.z = fmaf(s4.z, w6.x, fmaf(s4.w, w6.y, fmaf(s5.x, w6.z, fmaf(xb.z, w6.w, bb.z))));
    ob.w = fmaf(s5.y, w7.x, fmaf(s5.z, w7.y, fmaf(s5.w, w7.z, fmaf(xb.w, w7.w, bb.w))));

    // ---- new_state flat (24 floats):
    // {S1,S2,X0, S4,S5,X1, S7,S8,X2, S10,S11,X3, S13,S14,X4, S16,S17,X5, S19,S20,X6, S22,S23,X7}
    const float4 n0 = make_float4(s0.y, s0.z, xa.x, s1.x);    // S1,S2,X0,S4
    const float4 n1 = make_float4(s1.y, xa.y, s1.w, s2.x);    // S5,X1,S7,S8
    const float4 n2 = make_float4(xa.z, s2.z, s2.w, xa.w);    // X2,S10,S11,X3
    const float4 n3 = make_float4(s3.y, s3.z, xb.x, s4.x);    // S13,S14,X4,S16
    const float4 n4 = make_float4(s4.y, xb.y, s4.w, s5.x);    // S17,X5,S19,S20
    const float4 n5 = make_float4(xb.z, s5.z, s5.w, xb.w);    // X6,S22,S23,X7

    // ---- stores (STG.128, coalesced) ----
    float4* op = reinterpret_cast<float4*>(out + p0);
    op[0] = oa;
    op[1] = ob;
    float4* np = reinterpret_cast<float4*>(new_state + p0 * 3);
    np[0] = n0;  np[1] = n1;  np[2] = n2;
    np[3] = n3;  np[4] = n4;  np[5] = n5;
}

extern "C" void kernel_launch(void* const* d_in, const int* in_sizes, int n_in,
                              void* d_out, int out_size)
{
    const float* x      = (const float*)d_in[0];
    const float* state  = (const float*)d_in[1];
    const float* weight = (const float*)d_in[2];
    const float* bias   = (const float*)d_in[3];

    float* out       = (float*)d_out;
    float* new_state = (float*)d_out + PAIRS;

    const int threads = 256;
    const int blocks  = (int)(NTHREADS_TOTAL / threads);   // 8192
    causal_conv1d_kernel<<<blocks, threads>>>(x, state, weight, bias, out, new_state);
}

// round 5
// speedup vs baseline: 1.3502x; 1.3502x over previous
#include <cuda_runtime.h>
#include <cstdint>

// CausalConv1d (R5): R4's 8-pairs-per-thread structure with the register cap
// REMOVED. R4's __launch_bounds__(256,8) forced 32 regs -> local spills
// (L1 70.5% vs DRAM 49.7%). Now ptxas can hold all 8 streaming float4 loads
// front-batched in registers (MLP_p1=8) without spilling.

#define HIDDEN 4096
#define BATCH  4096
#define PAIRS  ((int64_t)BATCH * HIDDEN)          // 16,777,216
#define PAIRS_PER_THREAD 8
#define NTHREADS_TOTAL (PAIRS / PAIRS_PER_THREAD) // 2,097,152

__global__ void __launch_bounds__(256)
causal_conv1d_kernel(const float* __restrict__ x,
                     const float* __restrict__ state,
                     const float* __restrict__ weight,   // [HIDDEN,4]
                     const float* __restrict__ bias,     // [HIDDEN]
                     float* __restrict__ out,            // [BATCH,HIDDEN]
                     float* __restrict__ new_state)      // [BATCH,HIDDEN,3]
{
    int64_t t = (int64_t)blockIdx.x * blockDim.x + threadIdx.x;

    int64_t p0 = t * PAIRS_PER_THREAD;        // 8 consecutive (b,h) pairs, same row
    int     h0 = (int)(p0 & (HIDDEN - 1));    // 8 consecutive h's (HIDDEN % 8 == 0)

    // ---- front-batched streaming loads (8x LDG.128, fully coalesced) ----
    const float4* xp = reinterpret_cast<const float4*>(x + p0);
    const float4 xa = xp[0];                  // X0..X3
    const float4 xb = xp[1];                  // X4..X7

    const float4* sp = reinterpret_cast<const float4*>(state + p0 * 3);
    const float4 s0 = sp[0];   // S0..S3
    const float4 s1 = sp[1];   // S4..S7
    const float4 s2 = sp[2];   // S8..S11
    const float4 s3 = sp[3];   // S12..S15
    const float4 s4 = sp[4];   // S16..S19
    const float4 s5 = sp[5];   // S20..S23

    // ---- weights/bias (L1/L2-resident: 64KB + 16KB, reused 4096x) ----
    const float4* wp = reinterpret_cast<const float4*>(weight + (int64_t)h0 * 4);
    const float4 w0 = wp[0], w1 = wp[1], w2 = wp[2], w3 = wp[3];
    const float4 w4 = wp[4], w5 = wp[5], w6 = wp[6], w7 = wp[7];
    const float4* bp = reinterpret_cast<const float4*>(bias + h0);
    const float4 ba = bp[0], bb = bp[1];

    // ---- compute: pair j uses S[3j],S[3j+1],S[3j+2], X[j] ----
    float4 oa, ob;
    oa.x = fmaf(s0.x, w0.x, fmaf(s0.y, w0.y, fmaf(s0.z, w0.z, fmaf(xa.x, w0.w, ba.x))));
    oa.y = fmaf(s0.w, w1.x, fmaf(s1.x, w1.y, fmaf(s1.y, w1.z, fmaf(xa.y, w1.w, ba.y))));
    oa.z = fmaf(s1.z, w2.x, fmaf(s1.w, w2.y, fmaf(s2.x, w2.z, fmaf(xa.z, w2.w, ba.z))));
    oa.w = fmaf(s2.y, w3.x, fmaf(s2.z, w3.y, fmaf(s2.w, w3.z, fmaf(xa.w, w3.w, ba.w))));
    ob.x = fmaf(s3.x, w4.x, fmaf(s3.y, w4.y, fmaf(s3.z, w4.z, fmaf(xb.x, w4.w, bb.x))));
    ob.y = fmaf(s3.w, w5.x, fmaf(s4.x, w5.y, fmaf(s4.y, w5.z, fmaf(xb.y, w5.w, bb.y))));
    ob.z = fmaf(s4.z, w6.x, fmaf(s4.w, w6.y, fmaf(s5.x, w6.z, fmaf(xb.z, w6.w, bb.z))));
    ob.w = fmaf(s5.y, w7.x, fmaf(s5.z, w7.y, fmaf(s5.w, w7.z, fmaf(xb.w, w7.w, bb.w))));

    // ---- new_state flat (24 floats):
    // {S1,S2,X0, S4,S5,X1, S7,S8,X2, S10,S11,X3, S13,S14,X4, S16,S17,X5, S19,S20,X6, S22,S23,X7}
    const float4 n0 = make_float4(s0.y, s0.z, xa.x, s1.x);    // S1,S2,X0,S4
    const float4 n1 = make_float4(s1.y, xa.y, s1.w, s2.x);    // S5,X1,S7,S8
    const float4 n2 = make_float4(xa.z, s2.z, s2.w, xa.w);    // X2,S10,S11,X3
    const float4 n3 = make_float4(s3.y, s3.z, xb.x, s4.x);    // S13,S14,X4,S16
    const float4 n4 = make_float4(s4.y, xb.y, s4.w, s5.x);    // S17,X5,S19,S20
    const float4 n5 = make_float4(xb.z, s5.z, s5.w, xb.w);    // X6,S22,S23,X7

    // ---- stores (8x STG.128, coalesced) ----
    float4* op = reinterpret_cast<float4*>(out + p0);
    op[0] = oa;
    op[1] = ob;
    float4* np = reinterpret_cast<float4*>(new_state + p0 * 3);
    np[0] = n0;  np[1] = n1;  np[2] = n2;
    np[3] = n3;  np[4] = n4;  np[5] = n5;
}

extern "C" void kernel_launch(void* const* d_in, const int* in_sizes, int n_in,
                              void* d_out, int out_size)
{
    const float* x      = (const float*)d_in[0];
    const float* state  = (const float*)d_in[1];
    const float* weight = (const float*)d_in[2];
    const float* bias   = (const float*)d_in[3];

    float* out       = (float*)d_out;
    float* new_state = (float*)d_out + PAIRS;

    const int threads = 256;
    const int blocks  = (int)(NTHREADS_TOTAL / threads);   // 8192
    causal_conv1d_kernel<<<blocks, threads>>>(x, state, weight, bias, out, new_state);
}

// round 6
// speedup vs baseline: 2.1773x; 1.6125x over previous
#include <cuda_runtime.h>
#include <cstdint>

// CausalConv1d (R6): R2 structure + weights/bias staged in shared memory.
// R2-R5 evidence: the per-thread weight gather (lane stride 64B -> 16 L1
// wavefronts per LDG) made L1tex the binding pipe (~2/3 of L1 work). Moving
// weights to smem (SoA per-tap, conflict-free LDS.128) frees L1tex for the
// 512MB stream.
//
// out[b,h] = S0*w[h,0]+S1*w[h,1]+S2*w[h,2]+x*w[h,3]+bias[h]
// new_state[b,h,:] = {state[b,h,1], state[b,h,2], x[b,h]}

#define HIDDEN 4096
#define BATCH  4096
#define PAIRS  ((int64_t)BATCH * HIDDEN)
#define TPB    256
#define PAIRS_PER_BLOCK (TPB * 4)    // 1024 consecutive pairs, single row segment

__global__ void __launch_bounds__(TPB)
causal_conv1d_kernel(const float* __restrict__ x,
                     const float* __restrict__ state,
                     const float* __restrict__ weight,   // [HIDDEN,4] row-major
                     const float* __restrict__ bias,     // [HIDDEN]
                     float* __restrict__ out,            // [BATCH,HIDDEN]
                     float* __restrict__ new_state)      // [BATCH,HIDDEN,3]
{
    __shared__ float w_s[4][PAIRS_PER_BLOCK];   // SoA: tap k, local h
    __shared__ float b_s[PAIRS_PER_BLOCK];

    const int tid = threadIdx.x;
    const int64_t blk_p0 = (int64_t)blockIdx.x * PAIRS_PER_BLOCK;
    const int hb = (int)(blk_p0 & (HIDDEN - 1));   // block's h base (1024-aligned)

    // ---- cooperative weight load + transpose (coalesced LDG, conflict-free STS) ----
    const float4* wslice = reinterpret_cast<const float4*>(weight + (int64_t)hb * 4);
    #pragma unroll
    for (int i = 0; i < 4; ++i) {
        int r = tid + i * TPB;                 // local h row [0,1024)
        float4 w = wslice[r];                  // lanes stride 16B -> coalesced
        w_s[0][r] = w.x;                       // lanes stride 4B -> conflict-free
        w_s[1][r] = w.y;
        w_s[2][r] = w.z;
        w_s[3][r] = w.w;
    }
    {
        const float4* bslice = reinterpret_cast<const float4*>(bias + hb);
        reinterpret_cast<float4*>(b_s)[tid] = bslice[tid];
    }
    __syncthreads();

    // ---- per-thread: 4 consecutive pairs ----
    const int64_t p0 = blk_p0 + (int64_t)tid * 4;
    const int hl = tid * 4;                    // local h offset

    // tap vectors from smem: lane stride 16B -> all banks distinct per phase
    const float4 t0 = *reinterpret_cast<const float4*>(&w_s[0][hl]);
    const float4 t1 = *reinterpret_cast<const float4*>(&w_s[1][hl]);
    const float4 t2 = *reinterpret_cast<const float4*>(&w_s[2][hl]);
    const float4 t3 = *reinterpret_cast<const float4*>(&w_s[3][hl]);
    const float4 bv = *reinterpret_cast<const float4*>(&b_s[hl]);

    // ---- streaming loads (4x LDG.128, fully coalesced) ----
    const float4 xv = *reinterpret_cast<const float4*>(x + p0);
    const float4* sp = reinterpret_cast<const float4*>(state + p0 * 3);
    const float4 s0 = sp[0];   // S0..S3
    const float4 s1 = sp[1];   // S4..S7
    const float4 s2 = sp[2];   // S8..S11

    // ---- compute: pair j taps = {S[3j],S[3j+1],S[3j+2],X[j]} x {t0,t1,t2,t3}[j] ----
    float4 ov;
    ov.x = fmaf(s0.x, t0.x, fmaf(s0.y, t1.x, fmaf(s0.z, t2.x, fmaf(xv.x, t3.x, bv.x))));
    ov.y = fmaf(s0.w, t0.y, fmaf(s1.x, t1.y, fmaf(s1.y, t2.y, fmaf(xv.y, t3.y, bv.y))));
    ov.z = fmaf(s1.z, t0.z, fmaf(s1.w, t1.z, fmaf(s2.x, t2.z, fmaf(xv.z, t3.z, bv.z))));
    ov.w = fmaf(s2.y, t0.w, fmaf(s2.z, t1.w, fmaf(s2.w, t2.w, fmaf(xv.w, t3.w, bv.w))));

    // ---- new_state flat = {S1,S2,X0, S4,S5,X1, S7,S8,X2, S10,S11,X3} ----
    const float4 n0 = make_float4(s0.y, s0.z, xv.x, s1.x);
    const float4 n1 = make_float4(s1.y, xv.y, s1.w, s2.x);
    const float4 n2 = make_float4(xv.z, s2.z, s2.w, xv.w);

    // ---- stores (4x STG.128, coalesced) ----
    *reinterpret_cast<float4*>(out + p0) = ov;
    float4* np = reinterpret_cast<float4*>(new_state + p0 * 3);
    np[0] = n0;
    np[1] = n1;
    np[2] = n2;
}

extern "C" void kernel_launch(void* const* d_in, const int* in_sizes, int n_in,
                              void* d_out, int out_size)
{
    const float* x      = (const float*)d_in[0];
    const float* state  = (const float*)d_in[1];
    const float* weight = (const float*)d_in[2];
    const float* bias   = (const float*)d_in[3];

    float* out       = (float*)d_out;
    float* new_state = (float*)d_out + PAIRS;

    const int blocks = (int)(PAIRS / PAIRS_PER_BLOCK);   // 16384
    causal_conv1d_kernel<<<blocks, TPB>>>(x, state, weight, bias, out, new_state);
}